// round 14
// baseline (speedup 1.0000x reference)
#include <cuda_runtime.h>
#include <cuda_bf16.h>
#include <cstdint>

// ---------------- problem constants ----------------
#define TPB    384         // 256 e1 (mma) workers + 128 decoder workers
#define E1T    256
#define GROUP  14          // batch elements per block (2 blocks / SM)
#define NBLK   293         // 293 * 14 = 4102 >= 4096
#define BTOT   4096

#define T_IN   96
#define T_OUTC 32
#define TT     128
#define INF    8
#define H1     64
#define NKT    5           // K tiles of 16 (K=72 padded to 80)
#define ARSU   68          // A row stride in uints (bf16 pairs); 68 mod 32 = 4 -> conflict-free
#define ABUFU  (16*ARSU)   // 1088 uints per A buffer
#define H1STR  68          // e2 weight row stride
#define HD_STR 20

// ---------------- smem layout (float offsets) ----------------
#define OFF_B2   0         // 8*5*4*32 uint2 = 10240 floats (packed bf16 B frags)
#define OFF_A    10240     // 2*1088 uints = 2176 (double-buffered bf16 [x|h]; h also read by e2)
#define OFF_W2   12416     // 272
#define OFF_W2HB 12688     // 8
#define OFF_U    12696     // 16 (padded)
#define OFF_WD1  12712     // 1280
#define OFF_HD   13992     // 560
#define OFF_WD2  14552     // 80
#define OFF_XT   14632     // 448 (tail u: 32 steps x 14 elems)
#define OFF_DOUT 15080     // 1792
#define OFF_TMP  16872     // 448
#define SMEM_FLOATS 17320  // 69280 bytes/block -> 2 blocks/SM

#define BARSYNC(id,cnt) asm volatile("bar.sync %0, %1;"   :: "r"(id), "r"(cnt) : "memory")
#define BARARR(id,cnt)  asm volatile("bar.arrive %0, %1;" :: "r"(id), "r"(cnt) : "memory")

// fast activations on the MUFU.TANH path (1 MUFU each)
__device__ __forceinline__ float tanhf_a(float v) {
    float r; asm("tanh.approx.f32 %0, %1;" : "=f"(r) : "f"(v)); return r;
}
__device__ __forceinline__ float sigf(float v) {
    return fmaf(0.5f, tanhf_a(0.5f * v), 0.5f);
}
__device__ __forceinline__ unsigned pack_bf16(float lo, float hi) {
    __nv_bfloat162 p = __floats2bfloat162_rn(lo, hi);   // .x = lo (low 16 bits)
    return *reinterpret_cast<unsigned*>(&p);
}
__device__ __forceinline__ float2 unpack_bf16(unsigned u) {
    return __bfloat1622float2(*reinterpret_cast<__nv_bfloat162*>(&u));
}
__device__ __forceinline__ void mma_bf16(float* c, const unsigned* a, unsigned b0, unsigned b1) {
    asm volatile(
        "mma.sync.aligned.m16n8k16.row.col.f32.bf16.bf16.f32 "
        "{%0,%1,%2,%3}, {%4,%5,%6,%7}, {%8,%9}, {%0,%1,%2,%3};"
        : "+f"(c[0]), "+f"(c[1]), "+f"(c[2]), "+f"(c[3])
        : "r"(a[0]), "r"(a[1]), "r"(a[2]), "r"(a[3]), "r"(b0), "r"(b1));
}

__global__ void __launch_bounds__(TPB, 2)
lstm_net_kernel(const float* __restrict__ x,
                const float* __restrict__ e1Wih, const float* __restrict__ e1Whh, const float* __restrict__ e1b,
                const float* __restrict__ e2Wih, const float* __restrict__ e2Whh, const float* __restrict__ e2b,
                const float* __restrict__ d1Wih, const float* __restrict__ d1Whh, const float* __restrict__ d1b,
                const float* __restrict__ d2Wih, const float* __restrict__ d2Whh, const float* __restrict__ d2b,
                const float* __restrict__ fc1W, const float* __restrict__ fc1b,
                const float* __restrict__ fc2W, const float* __restrict__ fc2b,
                float* __restrict__ out)
{
    extern __shared__ float sm[];
    const int tid  = threadIdx.x;
    const int e0g  = blockIdx.x * GROUP;

    // ================= init =================
    // B fragments (bf16 pairs), gate-interleaved: n' = unit*4 + gate
    if (tid < 256) {
        const int w = tid >> 5, lane = tid & 31;
        uint2* B2 = (uint2*)(sm + OFF_B2);
        #pragma unroll
        for (int kt = 0; kt < NKT; ++kt)
            #pragma unroll
            for (int nt = 0; nt < 4; ++nt) {
                int np = w * 32 + nt * 8 + (lane >> 2);
                int r  = (np & 3) * 64 + (np >> 2);       // W1 row = gate*64 + unit
                int k0 = kt * 16 + 2 * (lane & 3);
                float v[4];
                #pragma unroll
                for (int j = 0; j < 4; ++j) {
                    int k = k0 + (j >> 1) * 8 + (j & 1);
                    v[j] = (k < INF) ? e1Wih[r * INF + k]
                         : (k < INF + H1) ? e1Whh[r * H1 + (k - INF)] : 0.f;
                }
                B2[((w * NKT + kt) * 4 + nt) * 32 + lane] =
                    make_uint2(pack_bf16(v[0], v[1]), pack_bf16(v[2], v[3]));
            }
    }
    // zero A (bf16) buffers (x pad + h0 = 0)
    for (int idx = tid; idx < 2 * ABUFU; idx += TPB) ((unsigned*)(sm + OFF_A))[idx] = 0u;
    // small weights
    for (int idx = tid; idx < 4 * H1; idx += TPB) {
        int g = idx >> 6, k = idx & 63;
        sm[OFF_W2 + g * H1STR + k] = e2Wih[g * H1 + k];
    }
    if (tid < 4) { sm[OFF_W2HB + tid] = e2Whh[tid]; sm[OFF_W2HB + 4 + tid] = e2b[tid]; }
    for (int idx = tid; idx < 64 * 16; idx += TPB) {
        int j = idx >> 4, k = idx & 15;
        sm[OFF_WD1 + j * HD_STR + k] = d1Whh[j * 16 + k];
    }
    if (tid < 64) {
        sm[OFF_WD1 + tid * HD_STR + 16] = d1Wih[tid];
        sm[OFF_WD1 + tid * HD_STR + 17] = d1b[tid];
        int g = tid >> 4, k = tid & 15;
        sm[OFF_WD2 + g * HD_STR + k] = d2Wih[g * 16 + k];
    }
    if (tid < 4) {
        sm[OFF_WD2 + tid * HD_STR + 16] = d2Whh[tid];
        sm[OFF_WD2 + tid * HD_STR + 17] = d2b[tid];
    }
    for (int idx = tid; idx < 2 * GROUP * HD_STR; idx += TPB) sm[OFF_HD + idx] = 0.f;
    // stage tail u values: u[tt][e] = x[e, 64+tt, 0]
    for (int idx = tid; idx < T_OUTC * GROUP; idx += TPB) {
        int tt = idx / GROUP, e = idx - tt * GROUP;
        int eg = e0g + e; if (eg >= BTOT) eg = BTOT - 1;
        sm[OFF_XT + tt * GROUP + e] = x[(size_t)eg * (T_IN * INF) + (64 + tt) * INF];
    }
    __syncthreads();
    // x_0 into A[0] bf16 cols 0..7
    if (tid < GROUP * INF) {
        int e = tid >> 3, i = tid & 7;
        int eg = e0g + e; if (eg >= BTOT) eg = BTOT - 1;
        ((__nv_bfloat16*)((unsigned*)(sm + OFF_A)))[e * (2 * ARSU) + i] =
            __float2bfloat16_rn(x[(size_t)eg * (T_IN * INF) + i]);
    }
    __syncthreads();

    if (tid < E1T) {
        // =========================================================
        //   e1 worker group: BF16 m16n8k16 MMA LSTM (14 rows)
        //   warp w owns B columns [32w, 32w+32)
        // =========================================================
        const int w = tid >> 5, lane = tid & 31;
        const int gid = lane >> 2, tq = lane & 3;
        const bool qe = ((tq & 1) == 0);

        float bI[4], bF[4], bG[4], bO[4];
        int un[4];
        #pragma unroll
        for (int nt = 0; nt < 4; ++nt) {
            int u = 8 * w + 2 * nt + (tq >> 1);
            un[nt] = u;
            bI[nt] = e1b[u];
            bF[nt] = e1b[64 + u];
            bG[nt] = e1b[128 + u];
            bO[nt] = e1b[192 + u];
        }
        float cs[4];
        #pragma unroll
        for (int i = 0; i < 4; ++i) cs[i] = 0.f;

        const int xe = tid >> 3, xi = tid & 7;   // x loader role (tid<112)
        int xeg = e0g + xe; if (xeg >= BTOT) xeg = BTOT - 1;

        const uint2* __restrict__ B2 = (const uint2*)(sm + OFF_B2);

        for (int t = 0; t < T_IN; ++t) {
            if (t >= 2)      BARSYNC(3 + (t & 1), TPB);   // next buffer free (decoder done)
            else if (t == 1) BARSYNC(6, E1T);             // h0/x1 visible within e1

            const unsigned* __restrict__ Au = (const unsigned*)(sm + OFF_A) + (t & 1) * ABUFU;
            __nv_bfloat16* __restrict__ Anb =
                (__nv_bfloat16*)((unsigned*)(sm + OFF_A) + ((t + 1) & 1) * ABUFU);

            float xv = 0.f;
            if ((t + 1 < T_IN) && tid < GROUP * INF)
                xv = x[(size_t)xeg * (T_IN * INF) + (t + 1) * INF + xi];

            float acc[4][4];
            #pragma unroll
            for (int nt = 0; nt < 4; ++nt)
                #pragma unroll
                for (int i = 0; i < 4; ++i) acc[nt][i] = 0.f;

            #pragma unroll
            for (int kt = 0; kt < NKT; ++kt) {
                const unsigned* ap = Au + gid * ARSU + kt * 8 + tq;
                unsigned ah[4];
                ah[0] = ap[0];
                ah[1] = ap[8 * ARSU];
                ah[2] = ap[4];
                ah[3] = ap[8 * ARSU + 4];
                #pragma unroll
                for (int nt = 0; nt < 4; ++nt) {
                    uint2 b = B2[((w * NKT + kt) * 4 + nt) * 32 + lane];
                    mma_bf16(acc[nt], ah, b.x, b.y);
                }
            }

            // ---- LSTM cell epilogue: lane-pair gate exchange ----
            #pragma unroll
            for (int nt = 0; nt < 4; ++nt) {
                float c0 = acc[nt][0], c1 = acc[nt][1];
                float c2 = acc[nt][2], c3 = acc[nt][3];
                float v0 = qe ? c2 : c0, v1 = qe ? c3 : c1;
                float r0 = __shfl_xor_sync(0xffffffffu, v0, 1);
                float r1 = __shfl_xor_sync(0xffffffffu, v1, 1);
                float gi = qe ? c0 : r0;
                float gf = qe ? c1 : r1;
                float gg = qe ? r0 : c2;
                float go = qe ? r1 : c3;
                int row = gid + (qe ? 0 : 8);
                float cc  = cs[nt];
                float igv = sigf(gi + bI[nt]);
                float fgv = sigf(gf + bF[nt]);
                float ggv = tanhf_a(gg + bG[nt]);
                float ogv = sigf(go + bO[nt]);
                cc = fgv * cc + igv * ggv;
                cs[nt] = cc;
                Anb[row * (2 * ARSU) + 8 + un[nt]] = __float2bfloat16_rn(ogv * tanhf_a(cc));
            }
            if ((t + 1 < T_IN) && tid < GROUP * INF)
                Anb[xe * (2 * ARSU) + xi] = __float2bfloat16_rn(xv);

            BARARR(1 + (t & 1), TPB);                     // h(t) ready
        }
    } else {
        // =========================================================
        //     decoder worker group (128 thr, 1 internal bar/step)
        // =========================================================
        const int dt = tid - E1T;
        const int UD = dt & 15;
        const int EB = dt >> 4;              // 0..7; element pair (EB, EB+8)
        // e2 role (warps 8,9 only; dt<64): element dt>>2 (clamped), gate dt&3
        const int e2e = (dt >> 2) > 13 ? 13 : (dt >> 2);
        const int e2g = dt & 3;

        float c2 = 0.f, h2 = 0.f;            // e2 state (owner lanes (dt&3)==0, dt<56)
        float cd[2]  = {0.f, 0.f};           // d1 cell states
        float c2d[2] = {0.f, 0.f};           // d2 states (lanes UD==0)
        float h2d[2] = {0.f, 0.f};

        float w2hh[4], b2g[4];
        #pragma unroll
        for (int g = 0; g < 4; ++g) { w2hh[g] = sm[OFF_W2HB + g]; b2g[g] = sm[OFF_W2HB + 4 + g]; }
        float d1wi[4], d1wb[4];
        #pragma unroll
        for (int g = 0; g < 4; ++g) {
            int row = (g << 4) + UD;
            d1wi[g] = sm[OFF_WD1 + row * HD_STR + 16];
            d1wb[g] = sm[OFF_WD1 + row * HD_STR + 17];
        }
        float wd2w[4], d2bb[4], d2hh[4];
        #pragma unroll
        for (int g = 0; g < 4; ++g) {
            wd2w[g] = sm[OFF_WD2 + g * HD_STR + UD];
            d2bb[g] = sm[OFF_WD2 + g * HD_STR + 17];
            d2hh[g] = sm[OFF_WD2 + g * HD_STR + 16];
        }

        int pd = 0;
        for (int t = 0; t < TT; ++t) {
            const float* up;
            if (t < T_IN) {
                BARSYNC(1 + (t & 1), TPB);                // wait h(t)
                const unsigned* hbu = (const unsigned*)(sm + OFF_A) + ((t + 1) & 1) * ABUFU;
                float s = 0.f;
                if (dt < 64) {                             // warps 8,9 (warp-uniform)
                    const uint4* hr = (const uint4*)(hbu + e2e * ARSU + 4);
                    const float4* w2 = (const float4*)(sm + OFF_W2 + e2g * H1STR);
                    float s0 = 0.f, s1 = 0.f;
                    #pragma unroll
                    for (int k = 0; k < 8; ++k) {
                        uint4 hv = hr[k];
                        float2 p0 = unpack_bf16(hv.x);
                        float2 p1 = unpack_bf16(hv.y);
                        float2 p2 = unpack_bf16(hv.z);
                        float2 p3 = unpack_bf16(hv.w);
                        float4 b0 = w2[2 * k], b1 = w2[2 * k + 1];
                        s0 += p0.x * b0.x + p0.y * b0.y + p1.x * b0.z + p1.y * b0.w;
                        s1 += p2.x * b1.x + p2.y * b1.y + p3.x * b1.z + p3.y * b1.w;
                    }
                    s = s0 + s1;
                }
                BARARR(3 + (t & 1), TPB);                 // done reading h buffer
                if (dt < 64) {
                    float p1 = __shfl_down_sync(0xffffffffu, s, 1);
                    float p2 = __shfl_down_sync(0xffffffffu, s, 2);
                    float p3 = __shfl_down_sync(0xffffffffu, s, 3);
                    if ((dt & 3) == 0 && dt < 56) {
                        float g0 = s  + b2g[0] + w2hh[0] * h2;
                        float g1 = p1 + b2g[1] + w2hh[1] * h2;
                        float g2 = p2 + b2g[2] + w2hh[2] * h2;
                        float g3 = p3 + b2g[3] + w2hh[3] * h2;
                        c2 = sigf(g1) * c2 + sigf(g0) * tanhf_a(g2);
                        h2 = sigf(g3) * tanhf_a(c2);
                        sm[OFF_U + (dt >> 2)] = fmaxf(h2, 0.f);
                    }
                }
                up = sm + OFF_U;
            } else {
                up = sm + OFF_XT + (t - T_IN) * GROUP;    // pre-staged tail u
            }
            BARSYNC(5, TPB - E1T);            // u ready + hd(t-1) writes visible

            // ---- d1 (in=1, hidden=16): elems EB, EB+8; k-outer, weights hoisted ----
            float hnew[2] = {0.f, 0.f};
            {
                const float4* hd4 = (const float4*)(sm + OFF_HD) + pd * (GROUP * HD_STR / 4);
                float* hdn = sm + OFF_HD + (1 - pd) * (GROUP * HD_STR);
                const int e1i = EB + 8;
                const bool m1ok = (e1i < GROUP);
                float u0 = up[EB];
                float u1 = m1ok ? up[e1i] : 0.f;
                float a0[2], a1[2], a2[2], a3[2];
                a0[0] = d1wb[0] + d1wi[0] * u0;  a0[1] = d1wb[0] + d1wi[0] * u1;
                a1[0] = d1wb[1] + d1wi[1] * u0;  a1[1] = d1wb[1] + d1wi[1] * u1;
                a2[0] = d1wb[2] + d1wi[2] * u0;  a2[1] = d1wb[2] + d1wi[2] * u1;
                a3[0] = d1wb[3] + d1wi[3] * u0;  a3[1] = d1wb[3] + d1wi[3] * u1;
                #pragma unroll
                for (int k = 0; k < 4; ++k) {
                    float4 w0 = *(const float4*)(sm + OFF_WD1 + (( 0 + UD) * HD_STR) + 4 * k);
                    float4 w1 = *(const float4*)(sm + OFF_WD1 + ((16 + UD) * HD_STR) + 4 * k);
                    float4 w2v = *(const float4*)(sm + OFF_WD1 + ((32 + UD) * HD_STR) + 4 * k);
                    float4 w3 = *(const float4*)(sm + OFF_WD1 + ((48 + UD) * HD_STR) + 4 * k);
                    float4 av0 = hd4[EB * 5 + k];
                    float4 av1 = m1ok ? hd4[e1i * 5 + k] : make_float4(0.f, 0.f, 0.f, 0.f);
                    a0[0] += av0.x * w0.x + av0.y * w0.y + av0.z * w0.z + av0.w * w0.w;
                    a1[0] += av0.x * w1.x + av0.y * w1.y + av0.z * w1.z + av0.w * w1.w;
                    a2[0] += av0.x * w2v.x + av0.y * w2v.y + av0.z * w2v.z + av0.w * w2v.w;
                    a3[0] += av0.x * w3.x + av0.y * w3.y + av0.z * w3.z + av0.w * w3.w;
                    a0[1] += av1.x * w0.x + av1.y * w0.y + av1.z * w0.z + av1.w * w0.w;
                    a1[1] += av1.x * w1.x + av1.y * w1.y + av1.z * w1.z + av1.w * w1.w;
                    a2[1] += av1.x * w2v.x + av1.y * w2v.y + av1.z * w2v.z + av1.w * w2v.w;
                    a3[1] += av1.x * w3.x + av1.y * w3.y + av1.z * w3.z + av1.w * w3.w;
                }
                {
                    float ig = sigf(a0[0]), fg = sigf(a1[0]);
                    float gg = tanhf_a(a2[0]), og = sigf(a3[0]);
                    float c = fg * cd[0] + ig * gg;
                    cd[0] = c;
                    hnew[0] = og * tanhf_a(c);
                    hdn[EB * HD_STR + UD] = hnew[0];
                }
                if (m1ok) {
                    float ig = sigf(a0[1]), fg = sigf(a1[1]);
                    float gg = tanhf_a(a2[1]), og = sigf(a3[1]);
                    float c = fg * cd[1] + ig * gg;
                    cd[1] = c;
                    hnew[1] = og * tanhf_a(c);
                    hdn[e1i * HD_STR + UD] = hnew[1];
                }
            }

            // ---- d2: intra-16-lane butterfly on registers (no bar, no smem) ----
            float v0[2], v1[2], v2[2], v3[2];
            #pragma unroll
            for (int m = 0; m < 2; ++m) {
                v0[m] = hnew[m] * wd2w[0];
                v1[m] = hnew[m] * wd2w[1];
                v2[m] = hnew[m] * wd2w[2];
                v3[m] = hnew[m] * wd2w[3];
            }
            #pragma unroll
            for (int d = 1; d < 16; d <<= 1) {
                #pragma unroll
                for (int m = 0; m < 2; ++m) {
                    v0[m] += __shfl_xor_sync(0xffffffffu, v0[m], d);
                    v1[m] += __shfl_xor_sync(0xffffffffu, v1[m], d);
                    v2[m] += __shfl_xor_sync(0xffffffffu, v2[m], d);
                    v3[m] += __shfl_xor_sync(0xffffffffu, v3[m], d);
                }
            }
            if (UD == 0) {
                #pragma unroll
                for (int m = 0; m < 2; ++m) {
                    int e = EB + 8 * m;
                    if (e < GROUP) {
                        float g0 = v0[m] + d2bb[0] + d2hh[0] * h2d[m];
                        float g1 = v1[m] + d2bb[1] + d2hh[1] * h2d[m];
                        float g2 = v2[m] + d2bb[2] + d2hh[2] * h2d[m];
                        float g3 = v3[m] + d2bb[3] + d2hh[3] * h2d[m];
                        c2d[m] = sigf(g1) * c2d[m] + sigf(g0) * tanhf_a(g2);
                        h2d[m] = sigf(g3) * tanhf_a(c2d[m]);
                        sm[OFF_DOUT + e * TT + t] = h2d[m];
                    }
                }
            }
            pd ^= 1;
        }
    }
    __syncthreads();

    // ---------------- FC head (all 384 threads) ----------------
    #pragma unroll
    for (int r = 0; r < 2; ++r) {
        int idx = tid + TPB * r;
        if (idx < GROUP * 32) {
            int e = idx >> 5, j = idx & 31;
            float s = fc1b[j];
            const float4* dr = (const float4*)(sm + OFF_DOUT + e * TT);
            const float4* wr = (const float4*)(fc1W + j * TT);
            #pragma unroll 8
            for (int k = 0; k < 32; ++k) {
                float4 a = dr[k], b = wr[k];
                s += a.x * b.x + a.y * b.y + a.z * b.z + a.w * b.w;
            }
            sm[OFF_TMP + e * 32 + j] = s;
        }
    }
    __syncthreads();
    #pragma unroll
    for (int r = 0; r < 2; ++r) {
        int idx = tid + TPB * r;
        if (idx < GROUP * 32) {
            int e = idx >> 5, o = idx & 31;
            if (e0g + e < BTOT) {
                float s = fc2b[o];
                const float4* tr = (const float4*)(sm + OFF_TMP + e * 32);
                const float4* wr = (const float4*)(fc2W + o * 32);
                #pragma unroll
                for (int k = 0; k < 8; ++k) {
                    float4 a = tr[k], b = wr[k];
                    s += a.x * b.x + a.y * b.y + a.z * b.z + a.w * b.w;
                }
                out[(size_t)(e0g + e) * T_OUTC + o] = s;
            }
        }
    }
}

extern "C" void kernel_launch(void* const* d_in, const int* in_sizes, int n_in,
                              void* d_out, int out_size) {
    (void)in_sizes; (void)n_in; (void)out_size;
    const float* x      = (const float*)d_in[0];
    const float* e1Wih  = (const float*)d_in[1];
    const float* e1Whh  = (const float*)d_in[2];
    const float* e1b    = (const float*)d_in[3];
    const float* e2Wih  = (const float*)d_in[4];
    const float* e2Whh  = (const float*)d_in[5];
    const float* e2b    = (const float*)d_in[6];
    const float* d1Wih  = (const float*)d_in[7];
    const float* d1Whh  = (const float*)d_in[8];
    const float* d1b    = (const float*)d_in[9];
    const float* d2Wih  = (const float*)d_in[10];
    const float* d2Whh  = (const float*)d_in[11];
    const float* d2b    = (const float*)d_in[12];
    const float* fc1W   = (const float*)d_in[13];
    const float* fc1b   = (const float*)d_in[14];
    const float* fc2W   = (const float*)d_in[15];
    const float* fc2b   = (const float*)d_in[16];

    const size_t smem = SMEM_FLOATS * sizeof(float);  // 69280 B
    cudaFuncSetAttribute(lstm_net_kernel,
                         cudaFuncAttributeMaxDynamicSharedMemorySize, (int)smem);
    lstm_net_kernel<<<NBLK, TPB, smem>>>(x,
        e1Wih, e1Whh, e1b, e2Wih, e2Whh, e2b,
        d1Wih, d1Whh, d1b, d2Wih, d2Whh, d2b,
        fc1W, fc1b, fc2W, fc2b, (float*)d_out);
}

// round 15
// speedup vs baseline: 1.0688x; 1.0688x over previous
#include <cuda_runtime.h>
#include <cuda_bf16.h>
#include <cstdint>

// ---------------- problem constants ----------------
#define TPB    384         // 256 e1 (mma) workers + 128 decoder workers
#define E1T    256
#define GROUP  14          // batch elements per block (2 blocks / SM)
#define NBLK   293         // 293 * 14 = 4102 >= 4096
#define BTOT   4096

#define T_IN   96
#define T_OUTC 32
#define TT     128
#define INF    8
#define H1     64
#define NKT    5           // K tiles of 16 (K=72 padded to 80)
#define ARSU   40          // A row stride in uints; 40 mod 32 = 8 -> conflict-free LDS.64 phases
#define ABUFU  (16*ARSU)   // 640 uints per A buffer
#define H1STR  68          // e2 weight row stride
#define HD_STR 20

// ---------------- smem layout (float offsets) ----------------
#define OFF_B2    0        // 8*5*2*32 uint4 = 10240 floats (packed bf16 B frags, nt-paired)
#define OFF_A     10240    // 2*640 uints = 1280 (double-buffered bf16 [x|h]; h read by e2)
#define OFF_W2    11520    // 272
#define OFF_W2HB  11792    // 8
#define OFF_G2    11800    // 56
#define OFF_H2    11856    // 14
#define OFF_U     11870    // 14
#define OFF_WD1B  11884    // 64*10 = 640 (bf16 d1 Whh rows, stride 10 uints)
#define OFF_WD1IB 12524    // 128 (wi[64], b[64])
#define OFF_HD    12652    // 560
#define OFF_WD2   13212    // 80
#define OFF_G2D   13292    // 56
#define OFF_H2D   13348    // 16 (padded)
#define OFF_XT    13364    // 448 (tail u: 32 steps x 14 elems)
#define OFF_DOUT  13812    // 1792
#define OFF_TMP   15604    // 448
#define SMEM_FLOATS 16052  // 64208 bytes/block -> 2 blocks/SM

#define BARSYNC(id,cnt) asm volatile("bar.sync %0, %1;"   :: "r"(id), "r"(cnt) : "memory")
#define BARARR(id,cnt)  asm volatile("bar.arrive %0, %1;" :: "r"(id), "r"(cnt) : "memory")

// fast activations on the MUFU.TANH path (1 MUFU each)
__device__ __forceinline__ float tanhf_a(float v) {
    float r; asm("tanh.approx.f32 %0, %1;" : "=f"(r) : "f"(v)); return r;
}
__device__ __forceinline__ float sigf(float v) {
    return fmaf(0.5f, tanhf_a(0.5f * v), 0.5f);
}
__device__ __forceinline__ unsigned pack_bf16(float lo, float hi) {
    __nv_bfloat162 p = __floats2bfloat162_rn(lo, hi);   // .x = lo (low 16 bits)
    return *reinterpret_cast<unsigned*>(&p);
}
__device__ __forceinline__ float2 unpack_bf16(unsigned u) {
    return __bfloat1622float2(*reinterpret_cast<__nv_bfloat162*>(&u));
}
__device__ __forceinline__ void mma_bf16(float* c, const unsigned* a, unsigned b0, unsigned b1) {
    asm volatile(
        "mma.sync.aligned.m16n8k16.row.col.f32.bf16.bf16.f32 "
        "{%0,%1,%2,%3}, {%4,%5,%6,%7}, {%8,%9}, {%0,%1,%2,%3};"
        : "+f"(c[0]), "+f"(c[1]), "+f"(c[2]), "+f"(c[3])
        : "r"(a[0]), "r"(a[1]), "r"(a[2]), "r"(a[3]), "r"(b0), "r"(b1));
}

__global__ void __launch_bounds__(TPB, 2)
lstm_net_kernel(const float* __restrict__ x,
                const float* __restrict__ e1Wih, const float* __restrict__ e1Whh, const float* __restrict__ e1b,
                const float* __restrict__ e2Wih, const float* __restrict__ e2Whh, const float* __restrict__ e2b,
                const float* __restrict__ d1Wih, const float* __restrict__ d1Whh, const float* __restrict__ d1b,
                const float* __restrict__ d2Wih, const float* __restrict__ d2Whh, const float* __restrict__ d2b,
                const float* __restrict__ fc1W, const float* __restrict__ fc1b,
                const float* __restrict__ fc2W, const float* __restrict__ fc2b,
                float* __restrict__ out)
{
    extern __shared__ float sm[];
    const int tid  = threadIdx.x;
    const int e0g  = blockIdx.x * GROUP;

    // ================= init =================
    // B fragments (bf16), gate-interleaved n' = unit*4 + gate, nt-paired uint4.
    // K-permuted to match LDS.64 A loads: logical k = kt*16 + 4*(lane&3) + j.
    if (tid < 256) {
        const int w = tid >> 5, lane = tid & 31;
        uint4* B4 = (uint4*)(sm + OFF_B2);
        #pragma unroll
        for (int kt = 0; kt < NKT; ++kt)
            #pragma unroll
            for (int np = 0; np < 2; ++np) {
                unsigned pk[4];
                #pragma unroll
                for (int nt2 = 0; nt2 < 2; ++nt2) {
                    int nt = 2 * np + nt2;
                    int nc = w * 32 + nt * 8 + (lane >> 2);
                    int r  = (nc & 3) * 64 + (nc >> 2);    // W1 row = gate*64 + unit
                    float v[4];
                    #pragma unroll
                    for (int j = 0; j < 4; ++j) {
                        int k = kt * 16 + 4 * (lane & 3) + j;   // permuted logical k
                        v[j] = (k < INF) ? e1Wih[r * INF + k]
                             : (k < INF + H1) ? e1Whh[r * H1 + (k - INF)] : 0.f;
                    }
                    pk[2 * nt2]     = pack_bf16(v[0], v[1]);
                    pk[2 * nt2 + 1] = pack_bf16(v[2], v[3]);
                }
                B4[((w * NKT + kt) * 2 + np) * 32 + lane] = make_uint4(pk[0], pk[1], pk[2], pk[3]);
            }
    }
    // zero A (bf16) buffers (x pad + h0 = 0, K-pad cols 72..79 = 0)
    for (int idx = tid; idx < 2 * ABUFU; idx += TPB) ((unsigned*)(sm + OFF_A))[idx] = 0u;
    // e2 weights
    for (int idx = tid; idx < 4 * H1; idx += TPB) {
        int g = idx >> 6, k = idx & 63;
        sm[OFF_W2 + g * H1STR + k] = e2Wih[g * H1 + k];
    }
    if (tid < 4) { sm[OFF_W2HB + tid] = e2Whh[tid]; sm[OFF_W2HB + 4 + tid] = e2b[tid]; }
    // d1 Whh as bf16 pairs, row stride 10 uints
    for (int idx = tid; idx < 64 * 8; idx += TPB) {
        int j = idx >> 3, kk = idx & 7;
        ((unsigned*)sm)[OFF_WD1B + j * 10 + kk] =
            pack_bf16(d1Whh[j * 16 + 2 * kk], d1Whh[j * 16 + 2 * kk + 1]);
    }
    if (tid < 64) {
        sm[OFF_WD1IB + tid]      = d1Wih[tid];
        sm[OFF_WD1IB + 64 + tid] = d1b[tid];
        int g = tid >> 4, k = tid & 15;
        sm[OFF_WD2 + g * HD_STR + k] = d2Wih[g * 16 + k];
    }
    if (tid < 4) {
        sm[OFF_WD2 + tid * HD_STR + 16] = d2Whh[tid];
        sm[OFF_WD2 + tid * HD_STR + 17] = d2b[tid];
    }
    for (int idx = tid; idx < 2 * GROUP * HD_STR; idx += TPB) sm[OFF_HD + idx] = 0.f;
    if (tid < GROUP) { sm[OFF_H2 + tid] = 0.f; sm[OFF_H2D + tid] = 0.f; }
    // stage tail u values: u[tt][e] = x[e, 64+tt, 0]
    for (int idx = tid; idx < T_OUTC * GROUP; idx += TPB) {
        int tt = idx / GROUP, e = idx - tt * GROUP;
        int eg = e0g + e; if (eg >= BTOT) eg = BTOT - 1;
        sm[OFF_XT + tt * GROUP + e] = x[(size_t)eg * (T_IN * INF) + (64 + tt) * INF];
    }
    __syncthreads();
    // x_0 into A[0] bf16 cols 0..7 (logical order; row stride 80 bf16)
    if (tid < GROUP * INF) {
        int e = tid >> 3, i = tid & 7;
        int eg = e0g + e; if (eg >= BTOT) eg = BTOT - 1;
        ((__nv_bfloat16*)((unsigned*)(sm + OFF_A)))[e * (2 * ARSU) + i] =
            __float2bfloat16_rn(x[(size_t)eg * (T_IN * INF) + i]);
    }
    __syncthreads();

    if (tid < E1T) {
        // =========================================================
        //   e1 worker group: BF16 m16n8k16 MMA LSTM (14 rows)
        //   warp w owns B columns [32w, 32w+32)
        // =========================================================
        const int w = tid >> 5, lane = tid & 31;
        const int gid = lane >> 2, tq = lane & 3;
        const bool qe = ((tq & 1) == 0);

        float bI[4], bF[4], bG[4], bO[4];
        int un[4];
        #pragma unroll
        for (int nt = 0; nt < 4; ++nt) {
            int u = 8 * w + 2 * nt + (tq >> 1);
            un[nt] = u;
            bI[nt] = e1b[u];
            bF[nt] = e1b[64 + u];
            bG[nt] = e1b[128 + u];
            bO[nt] = e1b[192 + u];
        }
        float cs[4];
        #pragma unroll
        for (int i = 0; i < 4; ++i) cs[i] = 0.f;

        const int xe = tid >> 3, xi = tid & 7;   // x loader role (tid<112)
        int xeg = e0g + xe; if (xeg >= BTOT) xeg = BTOT - 1;

        const uint4* __restrict__ B4 = (const uint4*)(sm + OFF_B2);

        for (int t = 0; t < T_IN; ++t) {
            if (t >= 2)      BARSYNC(3 + (t & 1), TPB);   // next buffer free (decoder done)
            else if (t == 1) BARSYNC(6, E1T);             // h0/x1 visible within e1

            const uint2* __restrict__ Au2 = (const uint2*)(sm + OFF_A) + (t & 1) * (ABUFU / 2);
            __nv_bfloat16* __restrict__ Anb =
                (__nv_bfloat16*)((unsigned*)(sm + OFF_A) + ((t + 1) & 1) * ABUFU);

            float xv = 0.f;
            if ((t + 1 < T_IN) && tid < GROUP * INF)
                xv = x[(size_t)xeg * (T_IN * INF) + (t + 1) * INF + xi];

            float acc[4][4];
            #pragma unroll
            for (int nt = 0; nt < 4; ++nt)
                #pragma unroll
                for (int i = 0; i < 4; ++i) acc[nt][i] = 0.f;

            #pragma unroll
            for (int kt = 0; kt < NKT; ++kt) {
                uint2 lo = Au2[gid * (ARSU / 2) + kt * 4 + tq];
                uint2 hi = Au2[(gid + 8) * (ARSU / 2) + kt * 4 + tq];
                unsigned ah[4];
                ah[0] = lo.x;   // hw k 2tq..2tq+1   (logical 4tq..4tq+1)
                ah[1] = hi.x;
                ah[2] = lo.y;   // hw k 2tq+8..2tq+9 (logical 4tq+2..4tq+3)
                ah[3] = hi.y;
                #pragma unroll
                for (int np = 0; np < 2; ++np) {
                    uint4 bb = B4[((w * NKT + kt) * 2 + np) * 32 + lane];
                    mma_bf16(acc[2 * np],     ah, bb.x, bb.y);
                    mma_bf16(acc[2 * np + 1], ah, bb.z, bb.w);
                }
            }

            // ---- LSTM cell epilogue: lane-pair gate exchange ----
            #pragma unroll
            for (int nt = 0; nt < 4; ++nt) {
                float c0 = acc[nt][0], c1 = acc[nt][1];
                float c2 = acc[nt][2], c3 = acc[nt][3];
                float v0 = qe ? c2 : c0, v1 = qe ? c3 : c1;
                float r0 = __shfl_xor_sync(0xffffffffu, v0, 1);
                float r1 = __shfl_xor_sync(0xffffffffu, v1, 1);
                float gi = qe ? c0 : r0;
                float gf = qe ? c1 : r1;
                float gg = qe ? r0 : c2;
                float go = qe ? r1 : c3;
                int row = gid + (qe ? 0 : 8);
                float cc  = cs[nt];
                float igv = sigf(gi + bI[nt]);
                float fgv = sigf(gf + bF[nt]);
                float ggv = tanhf_a(gg + bG[nt]);
                float ogv = sigf(go + bO[nt]);
                cc = fgv * cc + igv * ggv;
                cs[nt] = cc;
                Anb[row * (2 * ARSU) + 8 + un[nt]] = __float2bfloat16_rn(ogv * tanhf_a(cc));
            }
            if ((t + 1 < T_IN) && tid < GROUP * INF)
                Anb[xe * (2 * ARSU) + xi] = __float2bfloat16_rn(xv);

            BARARR(1 + (t & 1), TPB);                     // h(t) ready
        }
    } else {
        // =========================================================
        //                 decoder worker group (128 thr)
        // =========================================================
        const int dt = tid - E1T;
        const int UD = dt & 15;
        const int EB = dt >> 4;              // 0..7
        float cd[2] = {0.f, 0.f};
        float c2  = 0.f;
        float c2d = 0.f;
        float d1wi[4], d1wb[4];
        #pragma unroll
        for (int g = 0; g < 4; ++g) {
            d1wi[g] = sm[OFF_WD1IB + (g << 4) + UD];
            d1wb[g] = sm[OFF_WD1IB + 64 + (g << 4) + UD];
        }

        int pd = 0;
        for (int t = 0; t < TT; ++t) {
            const float* up;
            if (t < T_IN) {
                BARSYNC(1 + (t & 1), TPB);                // wait h(t)
                // h_t as bf16 in the A operand buffer, cols 8..71 (uints 4..35)
                const unsigned* hbu = (const unsigned*)(sm + OFF_A) + ((t + 1) & 1) * ABUFU;
                float s = 0.f;
                if (dt < 4 * GROUP) {
                    int e = dt >> 2, g = dt & 3;
                    const uint4* hr = (const uint4*)(hbu + e * ARSU + 4);
                    const float4* w2 = (const float4*)(sm + OFF_W2 + g * H1STR);
                    float s0 = 0.f, s1 = 0.f;
                    #pragma unroll
                    for (int k = 0; k < 8; ++k) {
                        uint4 hv = hr[k];
                        float2 p0 = unpack_bf16(hv.x);
                        float2 p1 = unpack_bf16(hv.y);
                        float2 p2 = unpack_bf16(hv.z);
                        float2 p3 = unpack_bf16(hv.w);
                        float4 b0 = w2[2 * k], b1 = w2[2 * k + 1];
                        s0 += p0.x * b0.x + p0.y * b0.y + p1.x * b0.z + p1.y * b0.w;
                        s1 += p2.x * b1.x + p2.y * b1.y + p3.x * b1.z + p3.y * b1.w;
                    }
                    s = s0 + s1 + sm[OFF_W2HB + 4 + g] + sm[OFF_W2HB + g] * sm[OFF_H2 + e];
                }
                BARARR(3 + (t & 1), TPB);                 // done reading h buffer
                if (dt < 4 * GROUP) sm[OFF_G2 + dt] = s;
                BARSYNC(5, TPB - E1T);
                if (dt < GROUP) {
                    float ig = sigf(sm[OFF_G2 + dt * 4 + 0]);
                    float fg = sigf(sm[OFF_G2 + dt * 4 + 1]);
                    float gg = tanhf_a(sm[OFF_G2 + dt * 4 + 2]);
                    float og = sigf(sm[OFF_G2 + dt * 4 + 3]);
                    c2 = fg * c2 + ig * gg;
                    float h2 = og * tanhf_a(c2);
                    sm[OFF_H2 + dt] = h2;
                    sm[OFF_U + dt]  = fmaxf(h2, 0.f);
                }
                up = sm + OFF_U;
            } else {
                up = sm + OFF_XT + (t - T_IN) * GROUP;    // pre-staged tail u
            }
            BARSYNC(5, TPB - E1T);                        // u ready

            // ---- d1 (in=1, hidden=16): elems EB, EB+8; k-outer, bf16 weights ----
            {
                const float4* hd4 = (const float4*)(sm + OFF_HD) + pd * (GROUP * HD_STR / 4);
                float* hdn = sm + OFF_HD + (1 - pd) * (GROUP * HD_STR);
                const uint2* wbp = (const uint2*)((unsigned*)sm + OFF_WD1B);  // idx = row*5 + k
                const int e1i = EB + 8;
                const bool m1ok = (e1i < GROUP);
                float u0 = up[EB];
                float u1 = m1ok ? up[e1i] : 0.f;
                float a0[2], a1[2], a2[2], a3[2];
                a0[0] = d1wb[0] + d1wi[0] * u0;  a0[1] = d1wb[0] + d1wi[0] * u1;
                a1[0] = d1wb[1] + d1wi[1] * u0;  a1[1] = d1wb[1] + d1wi[1] * u1;
                a2[0] = d1wb[2] + d1wi[2] * u0;  a2[1] = d1wb[2] + d1wi[2] * u1;
                a3[0] = d1wb[3] + d1wi[3] * u0;  a3[1] = d1wb[3] + d1wi[3] * u1;
                #pragma unroll
                for (int k = 0; k < 4; ++k) {
                    uint2 W0 = wbp[UD * 5 + k];
                    uint2 W1 = wbp[(16 + UD) * 5 + k];
                    uint2 W2u = wbp[(32 + UD) * 5 + k];
                    uint2 W3 = wbp[(48 + UD) * 5 + k];
                    float2 w0a = unpack_bf16(W0.x),  w0b = unpack_bf16(W0.y);
                    float2 w1a = unpack_bf16(W1.x),  w1b = unpack_bf16(W1.y);
                    float2 w2a = unpack_bf16(W2u.x), w2b = unpack_bf16(W2u.y);
                    float2 w3a = unpack_bf16(W3.x),  w3b = unpack_bf16(W3.y);
                    float4 av0 = hd4[EB * 5 + k];
                    float4 av1 = m1ok ? hd4[e1i * 5 + k] : make_float4(0.f, 0.f, 0.f, 0.f);
                    a0[0] += av0.x * w0a.x + av0.y * w0a.y + av0.z * w0b.x + av0.w * w0b.y;
                    a1[0] += av0.x * w1a.x + av0.y * w1a.y + av0.z * w1b.x + av0.w * w1b.y;
                    a2[0] += av0.x * w2a.x + av0.y * w2a.y + av0.z * w2b.x + av0.w * w2b.y;
                    a3[0] += av0.x * w3a.x + av0.y * w3a.y + av0.z * w3b.x + av0.w * w3b.y;
                    a0[1] += av1.x * w0a.x + av1.y * w0a.y + av1.z * w0b.x + av1.w * w0b.y;
                    a1[1] += av1.x * w1a.x + av1.y * w1a.y + av1.z * w1b.x + av1.w * w1b.y;
                    a2[1] += av1.x * w2a.x + av1.y * w2a.y + av1.z * w2b.x + av1.w * w2b.y;
                    a3[1] += av1.x * w3a.x + av1.y * w3a.y + av1.z * w3b.x + av1.w * w3b.y;
                }
                {
                    float ig = sigf(a0[0]), fg = sigf(a1[0]);
                    float gg = tanhf_a(a2[0]), og = sigf(a3[0]);
                    float c = fg * cd[0] + ig * gg;
                    cd[0] = c;
                    hdn[EB * HD_STR + UD] = og * tanhf_a(c);
                }
                if (m1ok) {
                    float ig = sigf(a0[1]), fg = sigf(a1[1]);
                    float gg = tanhf_a(a2[1]), og = sigf(a3[1]);
                    float c = fg * cd[1] + ig * gg;
                    cd[1] = c;
                    hdn[e1i * HD_STR + UD] = og * tanhf_a(c);
                }
            }
            BARSYNC(5, TPB - E1T);

            // ---- d2 gates ----
            if (dt < 4 * GROUP) {
                int e = dt >> 2, g = dt & 3;
                float s = sm[OFF_WD2 + g * HD_STR + 17]
                        + sm[OFF_WD2 + g * HD_STR + 16] * sm[OFF_H2D + e];
                const float4* hr = (const float4*)(sm + OFF_HD + (1 - pd) * (GROUP * HD_STR) + e * HD_STR);
                #pragma unroll
                for (int k = 0; k < 4; ++k) {
                    float4 a = hr[k];
                    const float4 b = *(const float4*)(sm + OFF_WD2 + g * HD_STR + 4 * k);
                    s += a.x * b.x + a.y * b.y + a.z * b.z + a.w * b.w;
                }
                sm[OFF_G2D + dt] = s;
            }
            BARSYNC(5, TPB - E1T);

            // ---- d2 state -> dout[t] ----
            if (dt < GROUP) {
                float ig = sigf(sm[OFF_G2D + dt * 4 + 0]);
                float fg = sigf(sm[OFF_G2D + dt * 4 + 1]);
                float gg = tanhf_a(sm[OFF_G2D + dt * 4 + 2]);
                float og = sigf(sm[OFF_G2D + dt * 4 + 3]);
                c2d = fg * c2d + ig * gg;
                float hh = og * tanhf_a(c2d);
                sm[OFF_H2D + dt]           = hh;
                sm[OFF_DOUT + dt * TT + t] = hh;
            }
            pd ^= 1;
        }
    }
    __syncthreads();

    // ---------------- FC head (all 384 threads) ----------------
    #pragma unroll
    for (int r = 0; r < 2; ++r) {
        int idx = tid + TPB * r;
        if (idx < GROUP * 32) {
            int e = idx >> 5, j = idx & 31;
            float s = fc1b[j];
            const float4* dr = (const float4*)(sm + OFF_DOUT + e * TT);
            const float4* wr = (const float4*)(fc1W + j * TT);
            #pragma unroll 8
            for (int k = 0; k < 32; ++k) {
                float4 a = dr[k], b = wr[k];
                s += a.x * b.x + a.y * b.y + a.z * b.z + a.w * b.w;
            }
            sm[OFF_TMP + e * 32 + j] = s;
        }
    }
    __syncthreads();
    #pragma unroll
    for (int r = 0; r < 2; ++r) {
        int idx = tid + TPB * r;
        if (idx < GROUP * 32) {
            int e = idx >> 5, o = idx & 31;
            if (e0g + e < BTOT) {
                float s = fc2b[o];
                const float4* tr = (const float4*)(sm + OFF_TMP + e * 32);
                const float4* wr = (const float4*)(fc2W + o * 32);
                #pragma unroll
                for (int k = 0; k < 8; ++k) {
                    float4 a = tr[k], b = wr[k];
                    s += a.x * b.x + a.y * b.y + a.z * b.z + a.w * b.w;
                }
                out[(size_t)(e0g + e) * T_OUTC + o] = s;
            }
        }
    }
}

extern "C" void kernel_launch(void* const* d_in, const int* in_sizes, int n_in,
                              void* d_out, int out_size) {
    (void)in_sizes; (void)n_in; (void)out_size;
    const float* x      = (const float*)d_in[0];
    const float* e1Wih  = (const float*)d_in[1];
    const float* e1Whh  = (const float*)d_in[2];
    const float* e1b    = (const float*)d_in[3];
    const float* e2Wih  = (const float*)d_in[4];
    const float* e2Whh  = (const float*)d_in[5];
    const float* e2b    = (const float*)d_in[6];
    const float* d1Wih  = (const float*)d_in[7];
    const float* d1Whh  = (const float*)d_in[8];
    const float* d1b    = (const float*)d_in[9];
    const float* d2Wih  = (const float*)d_in[10];
    const float* d2Whh  = (const float*)d_in[11];
    const float* d2b    = (const float*)d_in[12];
    const float* fc1W   = (const float*)d_in[13];
    const float* fc1b   = (const float*)d_in[14];
    const float* fc2W   = (const float*)d_in[15];
    const float* fc2b   = (const float*)d_in[16];

    const size_t smem = SMEM_FLOATS * sizeof(float);  // 64208 B
    cudaFuncSetAttribute(lstm_net_kernel,
                         cudaFuncAttributeMaxDynamicSharedMemorySize, (int)smem);
    lstm_net_kernel<<<NBLK, TPB, smem>>>(x,
        e1Wih, e1Whh, e1b, e2Wih, e2Whh, e2b,
        d1Wih, d1Whh, d1b, d2Wih, d2Whh, d2b,
        fc1W, fc1b, fc2W, fc2b, (float*)d_out);
}

// round 16
// speedup vs baseline: 1.1042x; 1.0331x over previous
#include <cuda_runtime.h>
#include <cuda_bf16.h>
#include <cstdint>

// ---------------- problem constants ----------------
#define TPB    384         // 256 e1 (mma) workers + 128 decoder workers
#define E1T    256
#define GROUP  14          // batch elements per block (2 blocks / SM)
#define NBLK   293         // 293 * 14 = 4102 >= 4096
#define BTOT   4096

#define T_IN   96
#define T_OUTC 32
#define TT     128
#define INF    8
#define H1     64
#define NKT    5           // K tiles of 16 (K=72 padded to 80)
#define ARSU   40          // A row stride in uints; 40 mod 32 = 8 -> conflict-free LDS.64 phases
#define ABUFU  (16*ARSU)   // 640 uints per A buffer
#define H1STR  68          // e2 weight row stride
#define HD_STR 20

// ---------------- smem layout (float offsets) ----------------
#define OFF_B2    0        // 8*5*2*32 uint4 = 10240 floats (packed bf16 B frags, nt-paired)
#define OFF_A     10240    // 2*640 uints = 1280 (double-buffered bf16 [x|h]; h read by e2)
#define OFF_W2    11520    // 272
#define OFF_W2HB  11792    // 8
#define OFF_G2    11800    // 56
#define OFF_H2    11856    // 14
#define OFF_U     11870    // 14
#define OFF_WD1   11884    // 64*20 = 1280 (fp32 d1 weights; wi at +16, b at +17)
#define OFF_HD    13164    // 560
#define OFF_WD2   13724    // 80
#define OFF_G2D   13804    // 56
#define OFF_H2D   13860    // 16 (padded)
#define OFF_XT    13876    // 448 (tail u: 32 steps x 14 elems)
#define OFF_DOUT  14324    // 1792
#define OFF_TMP   16116    // 448
#define SMEM_FLOATS 16564  // 66256 bytes/block -> 2 blocks/SM

#define BARSYNC(id,cnt) asm volatile("bar.sync %0, %1;"   :: "r"(id), "r"(cnt) : "memory")
#define BARARR(id,cnt)  asm volatile("bar.arrive %0, %1;" :: "r"(id), "r"(cnt) : "memory")

// fast activations on the MUFU.TANH path (1 MUFU each)
__device__ __forceinline__ float tanhf_a(float v) {
    float r; asm("tanh.approx.f32 %0, %1;" : "=f"(r) : "f"(v)); return r;
}
__device__ __forceinline__ float sigf(float v) {
    return fmaf(0.5f, tanhf_a(0.5f * v), 0.5f);
}
__device__ __forceinline__ unsigned pack_bf16(float lo, float hi) {
    __nv_bfloat162 p = __floats2bfloat162_rn(lo, hi);   // .x = lo (low 16 bits)
    return *reinterpret_cast<unsigned*>(&p);
}
__device__ __forceinline__ float2 unpack_bf16(unsigned u) {
    return __bfloat1622float2(*reinterpret_cast<__nv_bfloat162*>(&u));
}
__device__ __forceinline__ void mma_bf16(float* c, const unsigned* a, unsigned b0, unsigned b1) {
    asm volatile(
        "mma.sync.aligned.m16n8k16.row.col.f32.bf16.bf16.f32 "
        "{%0,%1,%2,%3}, {%4,%5,%6,%7}, {%8,%9}, {%0,%1,%2,%3};"
        : "+f"(c[0]), "+f"(c[1]), "+f"(c[2]), "+f"(c[3])
        : "r"(a[0]), "r"(a[1]), "r"(a[2]), "r"(a[3]), "r"(b0), "r"(b1));
}

__global__ void __launch_bounds__(TPB, 2)
lstm_net_kernel(const float* __restrict__ x,
                const float* __restrict__ e1Wih, const float* __restrict__ e1Whh, const float* __restrict__ e1b,
                const float* __restrict__ e2Wih, const float* __restrict__ e2Whh, const float* __restrict__ e2b,
                const float* __restrict__ d1Wih, const float* __restrict__ d1Whh, const float* __restrict__ d1b,
                const float* __restrict__ d2Wih, const float* __restrict__ d2Whh, const float* __restrict__ d2b,
                const float* __restrict__ fc1W, const float* __restrict__ fc1b,
                const float* __restrict__ fc2W, const float* __restrict__ fc2b,
                float* __restrict__ out)
{
    extern __shared__ float sm[];
    const int tid  = threadIdx.x;
    const int e0g  = blockIdx.x * GROUP;

    // ================= init =================
    // B fragments (bf16), gate-interleaved n' = unit*4 + gate, nt-paired uint4.
    // K-permuted to match LDS.64 A loads: logical k = kt*16 + 4*(lane&3) + j.
    if (tid < 256) {
        const int w = tid >> 5, lane = tid & 31;
        uint4* B4 = (uint4*)(sm + OFF_B2);
        #pragma unroll
        for (int kt = 0; kt < NKT; ++kt)
            #pragma unroll
            for (int np = 0; np < 2; ++np) {
                unsigned pk[4];
                #pragma unroll
                for (int nt2 = 0; nt2 < 2; ++nt2) {
                    int nt = 2 * np + nt2;
                    int nc = w * 32 + nt * 8 + (lane >> 2);
                    int r  = (nc & 3) * 64 + (nc >> 2);    // W1 row = gate*64 + unit
                    float v[4];
                    #pragma unroll
                    for (int j = 0; j < 4; ++j) {
                        int k = kt * 16 + 4 * (lane & 3) + j;   // permuted logical k
                        v[j] = (k < INF) ? e1Wih[r * INF + k]
                             : (k < INF + H1) ? e1Whh[r * H1 + (k - INF)] : 0.f;
                    }
                    pk[2 * nt2]     = pack_bf16(v[0], v[1]);
                    pk[2 * nt2 + 1] = pack_bf16(v[2], v[3]);
                }
                B4[((w * NKT + kt) * 2 + np) * 32 + lane] = make_uint4(pk[0], pk[1], pk[2], pk[3]);
            }
    }
    // zero A (bf16) buffers (x pad + h0 = 0, K-pad cols 72..79 = 0)
    for (int idx = tid; idx < 2 * ABUFU; idx += TPB) ((unsigned*)(sm + OFF_A))[idx] = 0u;
    // e2 weights
    for (int idx = tid; idx < 4 * H1; idx += TPB) {
        int g = idx >> 6, k = idx & 63;
        sm[OFF_W2 + g * H1STR + k] = e2Wih[g * H1 + k];
    }
    if (tid < 4) { sm[OFF_W2HB + tid] = e2Whh[tid]; sm[OFF_W2HB + 4 + tid] = e2b[tid]; }
    // d1 weights fp32 (row stride 20; wi at +16, b at +17)
    for (int idx = tid; idx < 64 * 16; idx += TPB) {
        int j = idx >> 4, k = idx & 15;
        sm[OFF_WD1 + j * HD_STR + k] = d1Whh[j * 16 + k];
    }
    if (tid < 64) {
        sm[OFF_WD1 + tid * HD_STR + 16] = d1Wih[tid];
        sm[OFF_WD1 + tid * HD_STR + 17] = d1b[tid];
        int g = tid >> 4, k = tid & 15;
        sm[OFF_WD2 + g * HD_STR + k] = d2Wih[g * 16 + k];
    }
    if (tid < 4) {
        sm[OFF_WD2 + tid * HD_STR + 16] = d2Whh[tid];
        sm[OFF_WD2 + tid * HD_STR + 17] = d2b[tid];
    }
    for (int idx = tid; idx < 2 * GROUP * HD_STR; idx += TPB) sm[OFF_HD + idx] = 0.f;
    if (tid < GROUP) { sm[OFF_H2 + tid] = 0.f; sm[OFF_H2D + tid] = 0.f; }
    // stage tail u values: u[tt][e] = x[e, 64+tt, 0]
    for (int idx = tid; idx < T_OUTC * GROUP; idx += TPB) {
        int tt = idx / GROUP, e = idx - tt * GROUP;
        int eg = e0g + e; if (eg >= BTOT) eg = BTOT - 1;
        sm[OFF_XT + tt * GROUP + e] = x[(size_t)eg * (T_IN * INF) + (64 + tt) * INF];
    }
    __syncthreads();
    // x_0 into A[0] bf16 cols 0..7 (logical order; row stride 80 bf16)
    if (tid < GROUP * INF) {
        int e = tid >> 3, i = tid & 7;
        int eg = e0g + e; if (eg >= BTOT) eg = BTOT - 1;
        ((__nv_bfloat16*)((unsigned*)(sm + OFF_A)))[e * (2 * ARSU) + i] =
            __float2bfloat16_rn(x[(size_t)eg * (T_IN * INF) + i]);
    }
    __syncthreads();

    if (tid < E1T) {
        // =========================================================
        //   e1 worker group: BF16 m16n8k16 MMA LSTM (14 rows)
        //   warp w owns B columns [32w, 32w+32)
        // =========================================================
        const int w = tid >> 5, lane = tid & 31;
        const int gid = lane >> 2, tq = lane & 3;
        const bool qe = ((tq & 1) == 0);

        float bI[4], bF[4], bG[4], bO[4];
        int un[4];
        #pragma unroll
        for (int nt = 0; nt < 4; ++nt) {
            int u = 8 * w + 2 * nt + (tq >> 1);
            un[nt] = u;
            bI[nt] = e1b[u];
            bF[nt] = e1b[64 + u];
            bG[nt] = e1b[128 + u];
            bO[nt] = e1b[192 + u];
        }
        float cs[4];
        #pragma unroll
        for (int i = 0; i < 4; ++i) cs[i] = 0.f;

        const int xe = tid >> 3, xi = tid & 7;   // x loader role (tid<112)
        int xeg = e0g + xe; if (xeg >= BTOT) xeg = BTOT - 1;

        const uint4* __restrict__ B4 = (const uint4*)(sm + OFF_B2);

        for (int t = 0; t < T_IN; ++t) {
            if (t >= 2)      BARSYNC(3 + (t & 1), TPB);   // next buffer free (decoder done)
            else if (t == 1) BARSYNC(6, E1T);             // h0/x1 visible within e1

            const uint2* __restrict__ Au2 = (const uint2*)(sm + OFF_A) + (t & 1) * (ABUFU / 2);
            __nv_bfloat16* __restrict__ Anb =
                (__nv_bfloat16*)((unsigned*)(sm + OFF_A) + ((t + 1) & 1) * ABUFU);

            float xv = 0.f;
            if ((t + 1 < T_IN) && tid < GROUP * INF)
                xv = x[(size_t)xeg * (T_IN * INF) + (t + 1) * INF + xi];

            float acc[4][4];
            #pragma unroll
            for (int nt = 0; nt < 4; ++nt)
                #pragma unroll
                for (int i = 0; i < 4; ++i) acc[nt][i] = 0.f;

            #pragma unroll
            for (int kt = 0; kt < NKT; ++kt) {
                uint2 lo = Au2[gid * (ARSU / 2) + kt * 4 + tq];
                uint2 hi = Au2[(gid + 8) * (ARSU / 2) + kt * 4 + tq];
                unsigned ah[4];
                ah[0] = lo.x;
                ah[1] = hi.x;
                ah[2] = lo.y;
                ah[3] = hi.y;
                #pragma unroll
                for (int np = 0; np < 2; ++np) {
                    uint4 bb = B4[((w * NKT + kt) * 2 + np) * 32 + lane];
                    mma_bf16(acc[2 * np],     ah, bb.x, bb.y);
                    mma_bf16(acc[2 * np + 1], ah, bb.z, bb.w);
                }
            }

            // ---- LSTM cell epilogue: lane-pair gate exchange ----
            #pragma unroll
            for (int nt = 0; nt < 4; ++nt) {
                float c0 = acc[nt][0], c1 = acc[nt][1];
                float c2 = acc[nt][2], c3 = acc[nt][3];
                float v0 = qe ? c2 : c0, v1 = qe ? c3 : c1;
                float r0 = __shfl_xor_sync(0xffffffffu, v0, 1);
                float r1 = __shfl_xor_sync(0xffffffffu, v1, 1);
                float gi = qe ? c0 : r0;
                float gf = qe ? c1 : r1;
                float gg = qe ? r0 : c2;
                float go = qe ? r1 : c3;
                int row = gid + (qe ? 0 : 8);
                float cc  = cs[nt];
                float igv = sigf(gi + bI[nt]);
                float fgv = sigf(gf + bF[nt]);
                float ggv = tanhf_a(gg + bG[nt]);
                float ogv = sigf(go + bO[nt]);
                cc = fgv * cc + igv * ggv;
                cs[nt] = cc;
                Anb[row * (2 * ARSU) + 8 + un[nt]] = __float2bfloat16_rn(ogv * tanhf_a(cc));
            }
            if ((t + 1 < T_IN) && tid < GROUP * INF)
                Anb[xe * (2 * ARSU) + xi] = __float2bfloat16_rn(xv);

            BARARR(1 + (t & 1), TPB);                     // h(t) ready
        }
    } else {
        // =========================================================
        //                 decoder worker group (128 thr)
        // =========================================================
        const int dt = tid - E1T;
        const int UD = dt & 15;
        const int EB = dt >> 4;              // 0..7
        float cd[2] = {0.f, 0.f};
        float c2  = 0.f;
        float c2d = 0.f;
        float d1wi[4], d1wb[4];
        #pragma unroll
        for (int g = 0; g < 4; ++g) {
            int row = (g << 4) + UD;
            d1wi[g] = sm[OFF_WD1 + row * HD_STR + 16];
            d1wb[g] = sm[OFF_WD1 + row * HD_STR + 17];
        }

        int pd = 0;
        for (int t = 0; t < TT; ++t) {
            const float* up;
            if (t < T_IN) {
                BARSYNC(1 + (t & 1), TPB);                // wait h(t)
                // h_t as bf16 in the A operand buffer, cols 8..71 (uints 4..35)
                const unsigned* hbu = (const unsigned*)(sm + OFF_A) + ((t + 1) & 1) * ABUFU;
                float s = 0.f;
                if (dt < 4 * GROUP) {
                    int e = dt >> 2, g = dt & 3;
                    const uint4* hr = (const uint4*)(hbu + e * ARSU + 4);
                    const float4* w2 = (const float4*)(sm + OFF_W2 + g * H1STR);
                    float s0 = 0.f, s1 = 0.f;
                    #pragma unroll
                    for (int k = 0; k < 8; ++k) {
                        uint4 hv = hr[k];
                        float2 p0 = unpack_bf16(hv.x);
                        float2 p1 = unpack_bf16(hv.y);
                        float2 p2 = unpack_bf16(hv.z);
                        float2 p3 = unpack_bf16(hv.w);
                        float4 b0 = w2[2 * k], b1 = w2[2 * k + 1];
                        s0 += p0.x * b0.x + p0.y * b0.y + p1.x * b0.z + p1.y * b0.w;
                        s1 += p2.x * b1.x + p2.y * b1.y + p3.x * b1.z + p3.y * b1.w;
                    }
                    s = s0 + s1 + sm[OFF_W2HB + 4 + g] + sm[OFF_W2HB + g] * sm[OFF_H2 + e];
                }
                BARARR(3 + (t & 1), TPB);                 // done reading h buffer
                if (dt < 4 * GROUP) sm[OFF_G2 + dt] = s;
                BARSYNC(5, TPB - E1T);
                if (dt < GROUP) {
                    float ig = sigf(sm[OFF_G2 + dt * 4 + 0]);
                    float fg = sigf(sm[OFF_G2 + dt * 4 + 1]);
                    float gg = tanhf_a(sm[OFF_G2 + dt * 4 + 2]);
                    float og = sigf(sm[OFF_G2 + dt * 4 + 3]);
                    c2 = fg * c2 + ig * gg;
                    float h2 = og * tanhf_a(c2);
                    sm[OFF_H2 + dt] = h2;
                    sm[OFF_U + dt]  = fmaxf(h2, 0.f);
                }
                up = sm + OFF_U;
            } else {
                up = sm + OFF_XT + (t - T_IN) * GROUP;    // pre-staged tail u
            }
            BARSYNC(5, TPB - E1T);                        // u ready

            // ---- d1 (in=1, hidden=16): elems EB, EB+8; k-outer, fp32 weights hoisted ----
            {
                const float4* hd4 = (const float4*)(sm + OFF_HD) + pd * (GROUP * HD_STR / 4);
                float* hdn = sm + OFF_HD + (1 - pd) * (GROUP * HD_STR);
                const int e1i = EB + 8;
                const bool m1ok = (e1i < GROUP);
                float u0 = up[EB];
                float u1 = m1ok ? up[e1i] : 0.f;
                float a0[2], a1[2], a2[2], a3[2];
                a0[0] = d1wb[0] + d1wi[0] * u0;  a0[1] = d1wb[0] + d1wi[0] * u1;
                a1[0] = d1wb[1] + d1wi[1] * u0;  a1[1] = d1wb[1] + d1wi[1] * u1;
                a2[0] = d1wb[2] + d1wi[2] * u0;  a2[1] = d1wb[2] + d1wi[2] * u1;
                a3[0] = d1wb[3] + d1wi[3] * u0;  a3[1] = d1wb[3] + d1wi[3] * u1;
                #pragma unroll
                for (int k = 0; k < 4; ++k) {
                    float4 w0 = *(const float4*)(sm + OFF_WD1 + (( 0 + UD) * HD_STR) + 4 * k);
                    float4 w1 = *(const float4*)(sm + OFF_WD1 + ((16 + UD) * HD_STR) + 4 * k);
                    float4 w2v = *(const float4*)(sm + OFF_WD1 + ((32 + UD) * HD_STR) + 4 * k);
                    float4 w3 = *(const float4*)(sm + OFF_WD1 + ((48 + UD) * HD_STR) + 4 * k);
                    float4 av0 = hd4[EB * 5 + k];
                    float4 av1 = m1ok ? hd4[e1i * 5 + k] : make_float4(0.f, 0.f, 0.f, 0.f);
                    a0[0] += av0.x * w0.x + av0.y * w0.y + av0.z * w0.z + av0.w * w0.w;
                    a1[0] += av0.x * w1.x + av0.y * w1.y + av0.z * w1.z + av0.w * w1.w;
                    a2[0] += av0.x * w2v.x + av0.y * w2v.y + av0.z * w2v.z + av0.w * w2v.w;
                    a3[0] += av0.x * w3.x + av0.y * w3.y + av0.z * w3.z + av0.w * w3.w;
                    a0[1] += av1.x * w0.x + av1.y * w0.y + av1.z * w0.z + av1.w * w0.w;
                    a1[1] += av1.x * w1.x + av1.y * w1.y + av1.z * w1.z + av1.w * w1.w;
                    a2[1] += av1.x * w2v.x + av1.y * w2v.y + av1.z * w2v.z + av1.w * w2v.w;
                    a3[1] += av1.x * w3.x + av1.y * w3.y + av1.z * w3.z + av1.w * w3.w;
                }
                {
                    float ig = sigf(a0[0]), fg = sigf(a1[0]);
                    float gg = tanhf_a(a2[0]), og = sigf(a3[0]);
                    float c = fg * cd[0] + ig * gg;
                    cd[0] = c;
                    hdn[EB * HD_STR + UD] = og * tanhf_a(c);
                }
                if (m1ok) {
                    float ig = sigf(a0[1]), fg = sigf(a1[1]);
                    float gg = tanhf_a(a2[1]), og = sigf(a3[1]);
                    float c = fg * cd[1] + ig * gg;
                    cd[1] = c;
                    hdn[e1i * HD_STR + UD] = og * tanhf_a(c);
                }
            }
            BARSYNC(5, TPB - E1T);

            // ---- d2 gates ----
            if (dt < 4 * GROUP) {
                int e = dt >> 2, g = dt & 3;
                float s = sm[OFF_WD2 + g * HD_STR + 17]
                        + sm[OFF_WD2 + g * HD_STR + 16] * sm[OFF_H2D + e];
                const float4* hr = (const float4*)(sm + OFF_HD + (1 - pd) * (GROUP * HD_STR) + e * HD_STR);
                #pragma unroll
                for (int k = 0; k < 4; ++k) {
                    float4 a = hr[k];
                    const float4 b = *(const float4*)(sm + OFF_WD2 + g * HD_STR + 4 * k);
                    s += a.x * b.x + a.y * b.y + a.z * b.z + a.w * b.w;
                }
                sm[OFF_G2D + dt] = s;
            }
            BARSYNC(5, TPB - E1T);

            // ---- d2 state -> dout[t] ----
            if (dt < GROUP) {
                float ig = sigf(sm[OFF_G2D + dt * 4 + 0]);
                float fg = sigf(sm[OFF_G2D + dt * 4 + 1]);
                float gg = tanhf_a(sm[OFF_G2D + dt * 4 + 2]);
                float og = sigf(sm[OFF_G2D + dt * 4 + 3]);
                c2d = fg * c2d + ig * gg;
                float hh = og * tanhf_a(c2d);
                sm[OFF_H2D + dt]           = hh;
                sm[OFF_DOUT + dt * TT + t] = hh;
            }
            pd ^= 1;
        }
    }
    __syncthreads();

    // ---------------- FC head (all 384 threads) ----------------
    #pragma unroll
    for (int r = 0; r < 2; ++r) {
        int idx = tid + TPB * r;
        if (idx < GROUP * 32) {
            int e = idx >> 5, j = idx & 31;
            float s = fc1b[j];
            const float4* dr = (const float4*)(sm + OFF_DOUT + e * TT);
            const float4* wr = (const float4*)(fc1W + j * TT);
            #pragma unroll 8
            for (int k = 0; k < 32; ++k) {
                float4 a = dr[k], b = wr[k];
                s += a.x * b.x + a.y * b.y + a.z * b.z + a.w * b.w;
            }
            sm[OFF_TMP + e * 32 + j] = s;
        }
    }
    __syncthreads();
    #pragma unroll
    for (int r = 0; r < 2; ++r) {
        int idx = tid + TPB * r;
        if (idx < GROUP * 32) {
            int e = idx >> 5, o = idx & 31;
            if (e0g + e < BTOT) {
                float s = fc2b[o];
                const float4* tr = (const float4*)(sm + OFF_TMP + e * 32);
                const float4* wr = (const float4*)(fc2W + o * 32);
                #pragma unroll
                for (int k = 0; k < 8; ++k) {
                    float4 a = tr[k], b = wr[k];
                    s += a.x * b.x + a.y * b.y + a.z * b.z + a.w * b.w;
                }
                out[(size_t)(e0g + e) * T_OUTC + o] = s;
            }
        }
    }
}

extern "C" void kernel_launch(void* const* d_in, const int* in_sizes, int n_in,
                              void* d_out, int out_size) {
    (void)in_sizes; (void)n_in; (void)out_size;
    const float* x      = (const float*)d_in[0];
    const float* e1Wih  = (const float*)d_in[1];
    const float* e1Whh  = (const float*)d_in[2];
    const float* e1b    = (const float*)d_in[3];
    const float* e2Wih  = (const float*)d_in[4];
    const float* e2Whh  = (const float*)d_in[5];
    const float* e2b    = (const float*)d_in[6];
    const float* d1Wih  = (const float*)d_in[7];
    const float* d1Whh  = (const float*)d_in[8];
    const float* d1b    = (const float*)d_in[9];
    const float* d2Wih  = (const float*)d_in[10];
    const float* d2Whh  = (const float*)d_in[11];
    const float* d2b    = (const float*)d_in[12];
    const float* fc1W   = (const float*)d_in[13];
    const float* fc1b   = (const float*)d_in[14];
    const float* fc2W   = (const float*)d_in[15];
    const float* fc2b   = (const float*)d_in[16];

    const size_t smem = SMEM_FLOATS * sizeof(float);  // 66256 B
    cudaFuncSetAttribute(lstm_net_kernel,
                         cudaFuncAttributeMaxDynamicSharedMemorySize, (int)smem);
    lstm_net_kernel<<<NBLK, TPB, smem>>>(x,
        e1Wih, e1Whh, e1b, e2Wih, e2Whh, e2b,
        d1Wih, d1Whh, d1b, d2Wih, d2Whh, d2b,
        fc1W, fc1b, fc2W, fc2b, (float*)d_out);
}